// round 3
// baseline (speedup 1.0000x reference)
#include <cuda_runtime.h>
#include <math.h>
#include <stdint.h>

// Problem constants
#define Nn   2048
#define Cc   1024
#define Hh   8
#define HD   128
#define SCALE_F 25.0f
#define SIM_THRESH 0.75f

// ---------------- scratch (device globals; no allocation allowed) ----------------
__device__ float g_qkv[Nn * 3 * Cc];            // [n][3C] raw qkv GEMM output
__device__ float g_q[Hh * Nn * HD];             // qn * SCALE, head-major [h][n][d]
__device__ float g_k[Hh * Nn * HD];             // kn, head-major
__device__ float g_vflat[Nn * Cc];              // raw v, flat [n][h*128+d]
__device__ float g_vnflat[Nn * Cc];             // per-head-normalized v, flat
__device__ float g_vT[Hh * HD * Nn];            // raw v transposed, [h][d][n]
__device__ float g_sim[Nn * Nn];                // sum_h vn.vn (before /8)
__device__ float g_attn[(size_t)Hh * Nn * Nn];  // logits -> softmaxed attn per head

// =====================================================================
// 3xTF32 tensor-core NT GEMM: C[M,N] = A[M,K] @ B[N,K]^T   (fp32 in/out)
// BM=BN=128, BK=16, 256 threads, 8 warps as 4(M)x2(N), warp tile 32x64.
// Shared tiles stored in mma-fragment-permuted layout (conflict-free LDS).
// hi/lo split (3xTF32) done in registers after LDS -> ~fp32 accuracy.
// =====================================================================

__device__ __forceinline__ void split_tf32(float v, uint32_t& hi, uint32_t& lo)
{
    uint32_t h;
    asm("cvt.rna.tf32.f32 %0, %1;" : "=r"(h) : "f"(v));
    hi = h;
    lo = __float_as_uint(v - __uint_as_float(h));
}

__device__ __forceinline__ void mma_tf32(float c[4], const uint32_t a[4],
                                         uint32_t b0, uint32_t b1)
{
    asm volatile(
        "mma.sync.aligned.m16n8k8.row.col.f32.tf32.tf32.f32 "
        "{%0,%1,%2,%3}, {%4,%5,%6,%7}, {%8,%9}, {%0,%1,%2,%3};"
        : "+f"(c[0]), "+f"(c[1]), "+f"(c[2]), "+f"(c[3])
        : "r"(a[0]), "r"(a[1]), "r"(a[2]), "r"(a[3]), "r"(b0), "r"(b1));
}

__global__ __launch_bounds__(256, 2) void tgemm_nt(
    const float* __restrict__ A, const float* __restrict__ B, float* __restrict__ C,
    int M, int N, int K, int lda, int ldb, int ldc,
    long long strideA, long long strideB, long long strideC)
{
    A += (long long)blockIdx.z * strideA;
    B += (long long)blockIdx.z * strideB;
    C += (long long)blockIdx.z * strideC;

    const int bm = blockIdx.y * 128;
    const int bn = blockIdx.x * 128;

    // permuted tiles: A 128x16 -> [chunk(=mBlock*2+kStep)][lane][reg(4)]
    //                 B 128x16 -> [chunk(=nBlock*2+kStep)][lane][reg(2)]
    __shared__ float As[2][2048];
    __shared__ float Bs[2][2048];

    const int tid  = threadIdx.x;
    const int lane = tid & 31;
    const int wid  = tid >> 5;
    const int wm   = wid >> 1;   // 0..3
    const int wn   = wid & 1;    // 0..1

    float cacc[2][8][4];
    #pragma unroll
    for (int mt = 0; mt < 2; mt++)
        #pragma unroll
        for (int nt = 0; nt < 8; nt++)
            #pragma unroll
            for (int r = 0; r < 4; r++) cacc[mt][nt][r] = 0.f;

    float4 ra[2], rb[2];

    const int nK = K / 16;

    // ---- stage 0 load ----
    #pragma unroll
    for (int t = 0; t < 2; t++) {
        int idx = tid + t * 256;
        int row = idx >> 2;
        int k4  = (idx & 3) * 4;
        ra[t] = *reinterpret_cast<const float4*>(&A[(long long)(bm + row) * lda + k4]);
        rb[t] = *reinterpret_cast<const float4*>(&B[(long long)(bn + row) * ldb + k4]);
    }
    // ---- store stage 0 ----
    #pragma unroll
    for (int t = 0; t < 2; t++) {
        int idx = tid + t * 256;
        int row = idx >> 2;
        int k4  = (idx & 3) * 4;
        {   // A scatter
            int mBlock = row >> 4, mIn = row & 15, kStep = k4 >> 3;
            int reg   = (mIn >> 3) + ((k4 & 4) >> 1);
            int base  = (((mBlock * 2 + kStep) * 32) + (mIn & 7) * 4) * 4 + reg;
            As[0][base + 0]  = ra[t].x;
            As[0][base + 4]  = ra[t].y;
            As[0][base + 8]  = ra[t].z;
            As[0][base + 12] = ra[t].w;
        }
        {   // B scatter
            int nBlock = row >> 3, nIn = row & 7, kStep = k4 >> 3;
            int reg   = (k4 & 4) >> 2;
            int base  = (((nBlock * 2 + kStep) * 32) + nIn * 4) * 2 + reg;
            Bs[0][base + 0] = rb[t].x;
            Bs[0][base + 2] = rb[t].y;
            Bs[0][base + 4] = rb[t].z;
            Bs[0][base + 6] = rb[t].w;
        }
    }
    __syncthreads();

    for (int it = 0; it < nK; ++it) {
        const int cur = it & 1;
        const bool hasNext = (it + 1 < nK);

        if (hasNext) {
            int k0 = (it + 1) * 16;
            #pragma unroll
            for (int t = 0; t < 2; t++) {
                int idx = tid + t * 256;
                int row = idx >> 2;
                int k4  = (idx & 3) * 4;
                ra[t] = *reinterpret_cast<const float4*>(&A[(long long)(bm + row) * lda + k0 + k4]);
                rb[t] = *reinterpret_cast<const float4*>(&B[(long long)(bn + row) * ldb + k0 + k4]);
            }
        }

        // ---- compute 2 k8-steps from buffer cur ----
        #pragma unroll
        for (int ks = 0; ks < 2; ks++) {
            uint32_t ahi[2][4], alo[2][4];
            #pragma unroll
            for (int mt = 0; mt < 2; mt++) {
                const float4 av = *reinterpret_cast<const float4*>(
                    &As[cur][(((wm * 2 + mt) * 2 + ks) * 32 + lane) * 4]);
                split_tf32(av.x, ahi[mt][0], alo[mt][0]);
                split_tf32(av.y, ahi[mt][1], alo[mt][1]);
                split_tf32(av.z, ahi[mt][2], alo[mt][2]);
                split_tf32(av.w, ahi[mt][3], alo[mt][3]);
            }
            #pragma unroll
            for (int nt = 0; nt < 8; nt++) {
                const float2 bv = *reinterpret_cast<const float2*>(
                    &Bs[cur][(((wn * 8 + nt) * 2 + ks) * 32 + lane) * 2]);
                uint32_t bhi0, blo0, bhi1, blo1;
                split_tf32(bv.x, bhi0, blo0);
                split_tf32(bv.y, bhi1, blo1);
                #pragma unroll
                for (int mt = 0; mt < 2; mt++) {
                    mma_tf32(cacc[mt][nt], ahi[mt], bhi0, bhi1);   // hi*hi
                    mma_tf32(cacc[mt][nt], alo[mt], bhi0, bhi1);   // lo*hi
                    mma_tf32(cacc[mt][nt], ahi[mt], blo0, blo1);   // hi*lo
                }
            }
        }

        if (hasNext) {
            const int nxt = 1 - cur;
            #pragma unroll
            for (int t = 0; t < 2; t++) {
                int idx = tid + t * 256;
                int row = idx >> 2;
                int k4  = (idx & 3) * 4;
                {
                    int mBlock = row >> 4, mIn = row & 15, kStep = k4 >> 3;
                    int reg  = (mIn >> 3) + ((k4 & 4) >> 1);
                    int base = (((mBlock * 2 + kStep) * 32) + (mIn & 7) * 4) * 4 + reg;
                    As[nxt][base + 0]  = ra[t].x;
                    As[nxt][base + 4]  = ra[t].y;
                    As[nxt][base + 8]  = ra[t].z;
                    As[nxt][base + 12] = ra[t].w;
                }
                {
                    int nBlock = row >> 3, nIn = row & 7, kStep = k4 >> 3;
                    int reg  = (k4 & 4) >> 2;
                    int base = (((nBlock * 2 + kStep) * 32) + nIn * 4) * 2 + reg;
                    Bs[nxt][base + 0] = rb[t].x;
                    Bs[nxt][base + 2] = rb[t].y;
                    Bs[nxt][base + 4] = rb[t].z;
                    Bs[nxt][base + 6] = rb[t].w;
                }
            }
        }
        __syncthreads();
    }

    // ---- epilogue ----
    #pragma unroll
    for (int mt = 0; mt < 2; mt++) {
        #pragma unroll
        for (int nt = 0; nt < 8; nt++) {
            int row0 = bm + wm * 32 + mt * 16 + (lane >> 2);
            int col  = bn + wn * 64 + nt * 8 + (lane & 3) * 2;
            float2 v0 = make_float2(cacc[mt][nt][0], cacc[mt][nt][1]);
            float2 v1 = make_float2(cacc[mt][nt][2], cacc[mt][nt][3]);
            *reinterpret_cast<float2*>(&C[(long long)row0 * ldc + col]) = v0;
            *reinterpret_cast<float2*>(&C[(long long)(row0 + 8) * ldc + col]) = v1;
        }
    }
}

// ---------------- normalize: split qkv, L2-normalize per head, build layouts ----------------
__global__ __launch_bounds__(256) void normalize_kernel()
{
    const int n = blockIdx.x;
    const int w = threadIdx.x >> 5;   // head
    const int lane = threadIdx.x & 31;
    const float* base = g_qkv + (long long)n * (3 * Cc);

    float qv[4], kv[4], vv[4];
    #pragma unroll
    for (int r = 0; r < 4; r++) {
        int d = lane + 32 * r;
        qv[r] = base[0 * Cc + w * HD + d];
        kv[r] = base[1 * Cc + w * HD + d];
        vv[r] = base[2 * Cc + w * HD + d];
    }
    float sq = 0.f, sk = 0.f, sv = 0.f;
    #pragma unroll
    for (int r = 0; r < 4; r++) { sq += qv[r] * qv[r]; sk += kv[r] * kv[r]; sv += vv[r] * vv[r]; }
    #pragma unroll
    for (int o = 16; o > 0; o >>= 1) {
        sq += __shfl_xor_sync(0xffffffffu, sq, o);
        sk += __shfl_xor_sync(0xffffffffu, sk, o);
        sv += __shfl_xor_sync(0xffffffffu, sv, o);
    }
    const float iq = SCALE_F / sqrtf(sq);
    const float ik = 1.0f / sqrtf(sk);
    const float iv = 1.0f / sqrtf(sv);

    #pragma unroll
    for (int r = 0; r < 4; r++) {
        int d = lane + 32 * r;
        g_q[(long long)w * Nn * HD + (long long)n * HD + d] = qv[r] * iq;
        g_k[(long long)w * Nn * HD + (long long)n * HD + d] = kv[r] * ik;
        g_vflat[(long long)n * Cc + w * HD + d]  = vv[r];
        g_vnflat[(long long)n * Cc + w * HD + d] = vv[r] * iv;
        g_vT[(long long)w * HD * Nn + (long long)d * Nn + n] = vv[r];
    }
}

// ---------------- block reduction helpers ----------------
__device__ __forceinline__ float blockMax(float v, float* sh)
{
    int tid = threadIdx.x;
    #pragma unroll
    for (int o = 16; o > 0; o >>= 1) v = fmaxf(v, __shfl_xor_sync(0xffffffffu, v, o));
    __syncthreads();
    if ((tid & 31) == 0) sh[tid >> 5] = v;
    __syncthreads();
    if (tid == 0) { float r = sh[0]; for (int i = 1; i < 8; i++) r = fmaxf(r, sh[i]); sh[8] = r; }
    __syncthreads();
    return sh[8];
}

__device__ __forceinline__ float blockSum(float v, float* sh)
{
    int tid = threadIdx.x;
    #pragma unroll
    for (int o = 16; o > 0; o >>= 1) v += __shfl_xor_sync(0xffffffffu, v, o);
    __syncthreads();
    if ((tid & 31) == 0) sh[tid >> 5] = v;
    __syncthreads();
    if (tid == 0) { float r = sh[0]; for (int i = 1; i < 8; i++) r += sh[i]; sh[8] = r; }
    __syncthreads();
    return sh[8];
}

// ---------------- per-row masked-scaled softmax over logits (in place) ----------------
__global__ __launch_bounds__(256) void softmax_kernel(const float* __restrict__ cls)
{
    const int i = blockIdx.x;
    const int h = blockIdx.y;
    const int tid = threadIdx.x;
    float* row = g_attn + (size_t)h * Nn * Nn + (size_t)i * Nn;
    const float thr = cls[i] - 0.1f;

    __shared__ float sh[16];
    float lv[8];
    float m = -1e30f;
    #pragma unroll
    for (int r = 0; r < 8; r++) {
        int j = tid + 256 * r;
        float cj = cls[j];
        float l = (cj > thr) ? row[j] * cj : 0.f;
        lv[r] = l;
        m = fmaxf(m, l);
    }
    m = blockMax(m, sh);
    float s = 0.f;
    #pragma unroll
    for (int r = 0; r < 8; r++) { lv[r] = expf(lv[r] - m); s += lv[r]; }
    s = blockSum(s, sh);
    const float iz = 1.0f / s;
    #pragma unroll
    for (int r = 0; r < 8; r++) row[tid + 256 * r] = lv[r] * iz;
}

// ---------------- copy raw v into second half of x_out ----------------
__global__ __launch_bounds__(256) void copy_v_kernel(float* __restrict__ out)
{
    int idx = blockIdx.x * blockDim.x + threadIdx.x;
    if (idx >= Nn * Cc / 4) return;
    int n = idx / (Cc / 4);
    int c4 = idx % (Cc / 4);
    float4 v = reinterpret_cast<const float4*>(g_vflat)[(size_t)n * (Cc / 4) + c4];
    reinterpret_cast<float4*>(out)[(size_t)n * (2 * Cc / 4) + (Cc / 4) + c4] = v;
}

// ---------------- sim_round2: head-avg attn -> softmax -> mask(sim>0.75) -> renorm ----------------
__global__ __launch_bounds__(256) void simround2_kernel(float* __restrict__ out_sim)
{
    const int i = blockIdx.x;
    const int tid = threadIdx.x;
    __shared__ float sh[16];

    float s[8];
    #pragma unroll
    for (int r = 0; r < 8; r++) {
        int j = tid + 256 * r;
        float acc = 0.f;
        #pragma unroll
        for (int h = 0; h < 8; h++)
            acc += g_attn[(size_t)h * Nn * Nn + (size_t)i * Nn + j];
        s[r] = acc * 0.125f;
    }
    float m = -1e30f;
    #pragma unroll
    for (int r = 0; r < 8; r++) m = fmaxf(m, s[r]);
    m = blockMax(m, sh);
    float z = 0.f;
    #pragma unroll
    for (int r = 0; r < 8; r++) { s[r] = expf(s[r] - m); z += s[r]; }
    z = blockSum(z, sh);
    const float iz = 1.0f / z;

    float msum = 0.f;
    #pragma unroll
    for (int r = 0; r < 8; r++) {
        int j = tid + 256 * r;
        float mk = (g_sim[(size_t)i * Nn + j] * 0.125f > SIM_THRESH) ? 1.f : 0.f;
        s[r] = mk * s[r] * iz;
        msum += s[r];
    }
    msum = blockSum(msum, sh);
    const float inv = 1.0f / msum;
    #pragma unroll
    for (int r = 0; r < 8; r++)
        out_sim[(size_t)i * Nn + tid + 256 * r] = s[r] * inv;
}

// ---------------- host launcher ----------------
extern "C" void kernel_launch(void* const* d_in, const int* in_sizes, int n_in,
                              void* d_out, int out_size)
{
    const float* x   = (const float*)d_in[0];  // [2048,1024]
    const float* cls = (const float*)d_in[1];  // [2048]
    const float* W   = (const float*)d_in[3];  // [3072,1024]
    float* out = (float*)d_out;                // x_out [2048,2048] then sim [2048,2048]

    float *p_qkv, *p_q, *p_k, *p_vnflat, *p_vT, *p_sim, *p_attn;
    cudaGetSymbolAddress((void**)&p_qkv, g_qkv);
    cudaGetSymbolAddress((void**)&p_q, g_q);
    cudaGetSymbolAddress((void**)&p_k, g_k);
    cudaGetSymbolAddress((void**)&p_vnflat, g_vnflat);
    cudaGetSymbolAddress((void**)&p_vT, g_vT);
    cudaGetSymbolAddress((void**)&p_sim, g_sim);
    cudaGetSymbolAddress((void**)&p_attn, g_attn);

    // 1. qkv = x @ W^T : [2048,3072]
    tgemm_nt<<<dim3(3 * Cc / 128, Nn / 128, 1), 256>>>(
        x, W, p_qkv, Nn, 3 * Cc, Cc, Cc, Cc, 3 * Cc, 0, 0, 0);

    // 2. split + normalize
    normalize_kernel<<<Nn, 256>>>();

    // 3. sim_raw sums = vnflat @ vnflat^T : [2048,2048]
    tgemm_nt<<<dim3(Nn / 128, Nn / 128, 1), 256>>>(
        p_vnflat, p_vnflat, p_sim, Nn, Nn, Cc, Cc, Cc, Nn, 0, 0, 0);

    // 4. logits per head: qn_h @ kn_h^T (SCALE folded into qn), batched over heads
    tgemm_nt<<<dim3(Nn / 128, Nn / 128, Hh), 256>>>(
        p_q, p_k, p_attn, Nn, Nn, HD, HD, HD, Nn,
        (long long)Nn * HD, (long long)Nn * HD, (long long)Nn * Nn);

    // 5. masked scaled softmax in place
    softmax_kernel<<<dim3(Nn, Hh), 256>>>(cls);

    // 6. x = attn_h @ v_h : into first half columns of x_out, batched
    tgemm_nt<<<dim3(HD / 128, Nn / 128, Hh), 256>>>(
        p_attn, p_vT, out, Nn, HD, Nn, Nn, Nn, 2 * Cc,
        (long long)Nn * Nn, (long long)HD * Nn, (long long)HD);

    // 7. x_ori = raw v into second half columns of x_out
    copy_v_kernel<<<(Nn * Cc / 4 + 255) / 256, 256>>>(out);

    // 8. sim_round2 into second output region
    simround2_kernel<<<Nn, 256>>>(out + (size_t)Nn * 2 * Cc);
}

// round 4
// speedup vs baseline: 1.3739x; 1.3739x over previous
#include <cuda_runtime.h>
#include <math.h>
#include <stdint.h>

#define Nn 2048
#define Cc 1024
#define Hh 8
#define HD 128
#define SCALE_F 25.0f

// ---------------- scratch ----------------
__device__ float g_qkv[Nn * 3 * Cc];
__device__ float g_q[Hh * Nn * HD];
__device__ float g_k[Hh * Nn * HD];
__device__ float g_vn[Nn * Cc];
__device__ float g_vT[Hh * HD * Nn];
__device__ float g_sim[Nn * Nn];
__device__ float g_attn[(size_t)Hh * Nn * Nn];   // raw logits (scaled q . k)
__device__ float g_rowsum[Hh * Nn];

// packed operand images. tile = 128 rows x 16 k; 3 images x 1024 u32 = 768 uint4
__device__ uint4 g_xpA [(size_t)16 * 64 * 768];
__device__ uint4 g_WpB [(size_t)24 * 64 * 768];
__device__ uint4 g_qpA [(size_t)8 * 16 * 8 * 768];
__device__ uint4 g_kpB [(size_t)8 * 16 * 8 * 768];
__device__ uint4 g_vnpA[(size_t)16 * 64 * 768];
__device__ uint4 g_vnpB[(size_t)16 * 64 * 768];
__device__ uint4 g_vTpB[(size_t)8 * 128 * 768];
__device__ uint4 g_epk [(size_t)8 * 16 * 128 * 768];  // e-values, 2 images used

// ---------------- helpers ----------------
__device__ __forceinline__ uint32_t packbf(float x, float y)
{   // low 16 = bf16(x), high 16 = bf16(y)
    uint32_t h;
    asm("cvt.rn.bf16x2.f32 %0, %1, %2;" : "=r"(h) : "f"(y), "f"(x));
    return h;
}
__device__ __forceinline__ float blo(uint32_t u) { return __uint_as_float(u << 16); }
__device__ __forceinline__ float bhi(uint32_t u) { return __uint_as_float(u & 0xFFFF0000u); }

__device__ __forceinline__ void split2(float x, float y, uint32_t& s0, uint32_t& s1)
{
    s0 = packbf(x, y);
    s1 = packbf(x - blo(s0), y - bhi(s0));
}
__device__ __forceinline__ void split3(float x, float y, uint32_t& s0, uint32_t& s1, uint32_t& s2)
{
    s0 = packbf(x, y);
    float rx = x - blo(s0), ry = y - bhi(s0);
    s1 = packbf(rx, ry);
    s2 = packbf(rx - blo(s1), ry - bhi(s1));
}

__device__ __forceinline__ void mma_bf16(float c[4], const uint32_t a[4],
                                         uint32_t b0, uint32_t b1)
{
    asm volatile(
        "mma.sync.aligned.m16n8k16.row.col.f32.bf16.bf16.f32 "
        "{%0,%1,%2,%3}, {%4,%5,%6,%7}, {%8,%9}, {%0,%1,%2,%3};"
        : "+f"(c[0]), "+f"(c[1]), "+f"(c[2]), "+f"(c[3])
        : "r"(a[0]), "r"(a[1]), "r"(a[2]), "r"(a[3]), "r"(b0), "r"(b1));
}

// ---------------- pack kernels (fp32 -> 3-term bf16 fragment images) ----------------
// A image word: (m*32 + g*4 + t)*4 + reg ; m=row>>4, g=(row&15)&7, reg=((row&15)>>3)+2*(k>=8), t=(k&7)>>1
__global__ __launch_bounds__(256) void pack_a3(
    const float* __restrict__ src, int lda, long long zstride, uint4* __restrict__ dst, int nKb)
{
    const int kb = blockIdx.x, rb = blockIdx.y, z = blockIdx.z;
    src += (long long)z * zstride;
    uint32_t* tb = (uint32_t*)(dst + ((size_t)(z * gridDim.y + rb) * nKb + kb) * 768);
    const int tid = threadIdx.x;
    #pragma unroll
    for (int t = 0; t < 2; t++) {
        int idx = tid + t * 256;
        int row = idx >> 2, k4 = (idx & 3) * 4;
        float4 v = *reinterpret_cast<const float4*>(
            &src[(long long)(rb * 128 + row) * lda + kb * 16 + k4]);
        int m = row >> 4, r16 = row & 15, g = r16 & 7, half = r16 >> 3;
        int tt = (k4 & 7) >> 1, reg = half + 2 * (k4 >> 3);
        int base = (m * 32 + g * 4 + tt) * 4 + reg;
        uint32_t s0, s1, s2;
        split3(v.x, v.y, s0, s1, s2);
        tb[base] = s0; tb[1024 + base] = s1; tb[2048 + base] = s2;
        split3(v.z, v.w, s0, s1, s2);
        tb[base + 4] = s0; tb[1024 + base + 4] = s1; tb[2048 + base + 4] = s2;
    }
}

// B image word: (nb*32 + g*4 + t)*2 + reg ; nb=row>>3, g=row&7, reg=k>>3, t=(k&7)>>1
__global__ __launch_bounds__(256) void pack_b3(
    const float* __restrict__ src, int ldb, long long zstride, uint4* __restrict__ dst, int nKb)
{
    const int kb = blockIdx.x, rb = blockIdx.y, z = blockIdx.z;
    src += (long long)z * zstride;
    uint32_t* tb = (uint32_t*)(dst + ((size_t)(z * gridDim.y + rb) * nKb + kb) * 768);
    const int tid = threadIdx.x;
    #pragma unroll
    for (int t = 0; t < 2; t++) {
        int idx = tid + t * 256;
        int row = idx >> 2, k4 = (idx & 3) * 4;
        float4 v = *reinterpret_cast<const float4*>(
            &src[(long long)(rb * 128 + row) * ldb + kb * 16 + k4]);
        int nb = row >> 3, g = row & 7;
        int tt = (k4 & 7) >> 1, reg = k4 >> 3;
        int base = (nb * 32 + g * 4 + tt) * 2 + reg;
        uint32_t s0, s1, s2;
        split3(v.x, v.y, s0, s1, s2);
        tb[base] = s0; tb[1024 + base] = s1; tb[2048 + base] = s2;
        split3(v.z, v.w, s0, s1, s2);
        tb[base + 2] = s0; tb[1024 + base + 2] = s1; tb[2048 + base + 2] = s2;
    }
}

// ---------------- packed multi-term bf16 GEMM ----------------
// C[M,N] = A @ B^T on fragment images. 256 thr, warps 4(M)x2(N), CTA 128x128, BK=16.
// TERMS=2: products (0,0),(1,0),(0,1). TERMS=3: all i+j<3 (6 products).
template<int TERMS>
__global__ __launch_bounds__(256, 2) void gemm_pk(
    const uint4* __restrict__ At, const uint4* __restrict__ Bt, int nK,
    float* __restrict__ C, int ldc, long long cZ, const float* __restrict__ rs)
{
    const uint4* Ab = At + (size_t)(blockIdx.z * gridDim.y + blockIdx.y) * nK * 768;
    const uint4* Bb = Bt + (size_t)(blockIdx.z * gridDim.x + blockIdx.x) * nK * 768;
    float* Cz = C + (long long)blockIdx.z * cZ;

    __shared__ uint4 smA[2][768], smB[2][768];

    const int tid = threadIdx.x, lane = tid & 31, wid = tid >> 5;
    const int wm = wid >> 1, wn = wid & 1;

    float acc[2][8][4];
    #pragma unroll
    for (int mt = 0; mt < 2; mt++)
        #pragma unroll
        for (int nt = 0; nt < 8; nt++)
            #pragma unroll
            for (int r = 0; r < 4; r++) acc[mt][nt][r] = 0.f;

    uint4 ra[TERMS], rb[TERMS];
    #pragma unroll
    for (int i = 0; i < TERMS; i++) {
        smA[0][i * 256 + tid] = Ab[i * 256 + tid];
        smB[0][i * 256 + tid] = Bb[i * 256 + tid];
    }
    __syncthreads();

    for (int kb = 0; kb < nK; kb++) {
        const int cur = kb & 1;
        const bool nxt = (kb + 1 < nK);
        if (nxt) {
            const uint4* An = Ab + (size_t)(kb + 1) * 768;
            const uint4* Bn = Bb + (size_t)(kb + 1) * 768;
            #pragma unroll
            for (int i = 0; i < TERMS; i++) { ra[i] = An[i * 256 + tid]; rb[i] = Bn[i * 256 + tid]; }
        }

        uint32_t af[TERMS][2][4];
        #pragma unroll
        for (int i = 0; i < TERMS; i++)
            #pragma unroll
            for (int mt = 0; mt < 2; mt++)
                *reinterpret_cast<uint4*>(af[i][mt]) =
                    smA[cur][i * 256 + (wm * 2 + mt) * 32 + lane];

        const uint2* B2 = reinterpret_cast<const uint2*>(smB[cur]);
        #pragma unroll
        for (int nt = 0; nt < 8; nt++) {
            uint2 bf[TERMS];
            #pragma unroll
            for (int i = 0; i < TERMS; i++)
                bf[i] = B2[i * 512 + (wn * 8 + nt) * 32 + lane];
            #pragma unroll
            for (int i = 0; i < TERMS; i++)
                #pragma unroll
                for (int j = 0; j < TERMS; j++)
                    if (i + j < TERMS) {
                        #pragma unroll
                        for (int mt = 0; mt < 2; mt++)
                            mma_bf16(acc[mt][nt], af[i][mt], bf[j].x, bf[j].y);
                    }
        }

        if (nxt) {
            const int nb = cur ^ 1;
            #pragma unroll
            for (int i = 0; i < TERMS; i++) {
                smA[nb][i * 256 + tid] = ra[i];
                smB[nb][i * 256 + tid] = rb[i];
            }
        }
        __syncthreads();
    }

    const int g = lane >> 2, tq = lane & 3;
    #pragma unroll
    for (int mt = 0; mt < 2; mt++) {
        const int row0 = blockIdx.y * 128 + wm * 32 + mt * 16 + g;
        float s0 = 1.f, s1 = 1.f;
        if (rs) {
            s0 = 1.f / rs[blockIdx.z * Nn + row0];
            s1 = 1.f / rs[blockIdx.z * Nn + row0 + 8];
        }
        #pragma unroll
        for (int nt = 0; nt < 8; nt++) {
            const int col = blockIdx.x * 128 + wn * 64 + nt * 8 + tq * 2;
            *reinterpret_cast<float2*>(&Cz[(long long)row0 * ldc + col]) =
                make_float2(acc[mt][nt][0] * s0, acc[mt][nt][1] * s0);
            *reinterpret_cast<float2*>(&Cz[(long long)(row0 + 8) * ldc + col]) =
                make_float2(acc[mt][nt][2] * s1, acc[mt][nt][3] * s1);
        }
    }
}

// ---------------- normalize: split qkv, L2-normalize per head ----------------
__global__ __launch_bounds__(256) void normalize_kernel()
{
    const int n = blockIdx.x;
    const int w = threadIdx.x >> 5;
    const int lane = threadIdx.x & 31;
    const float* base = g_qkv + (long long)n * (3 * Cc);

    float qv[4], kv[4], vv[4];
    #pragma unroll
    for (int r = 0; r < 4; r++) {
        int d = lane + 32 * r;
        qv[r] = base[0 * Cc + w * HD + d];
        kv[r] = base[1 * Cc + w * HD + d];
        vv[r] = base[2 * Cc + w * HD + d];
    }
    float sq = 0.f, sk = 0.f, sv = 0.f;
    #pragma unroll
    for (int r = 0; r < 4; r++) { sq += qv[r]*qv[r]; sk += kv[r]*kv[r]; sv += vv[r]*vv[r]; }
    #pragma unroll
    for (int o = 16; o > 0; o >>= 1) {
        sq += __shfl_xor_sync(0xffffffffu, sq, o);
        sk += __shfl_xor_sync(0xffffffffu, sk, o);
        sv += __shfl_xor_sync(0xffffffffu, sv, o);
    }
    const float iq = SCALE_F / sqrtf(sq);
    const float ik = 1.0f / sqrtf(sk);
    const float iv = 1.0f / sqrtf(sv);
    #pragma unroll
    for (int r = 0; r < 4; r++) {
        int d = lane + 32 * r;
        g_q[(long long)w * Nn * HD + (long long)n * HD + d] = qv[r] * iq;
        g_k[(long long)w * Nn * HD + (long long)n * HD + d] = kv[r] * ik;
        g_vn[(long long)n * Cc + w * HD + d] = vv[r] * iv;
        g_vT[(long long)w * HD * Nn + (long long)d * Nn + n] = vv[r];
    }
}

// ---------------- softmax: logits -> unnormalized e (packed 2-term A-image) + rowsums ----------------
// block = (16-row group a, head h). warp w handles kb = w, w+8, ...
__global__ __launch_bounds__(256) void softmax_pack(const float* __restrict__ cls)
{
    const int a = blockIdx.x, h = blockIdx.y;
    const int i0 = a * 16, rowBlk = a >> 3, m = a & 7;
    const int tid = threadIdx.x, w = tid >> 5, lane = tid & 31;
    const int g = lane >> 2, t = lane & 3;
    const int ra = i0 + g, rb2 = ra + 8;
    const float tha = cls[ra] - 0.1f, thb = cls[rb2] - 0.1f;
    const float* La = g_attn + ((size_t)h * Nn + ra) * Nn;
    const float* Lb = g_attn + ((size_t)h * Nn + rb2) * Nn;
    uint32_t* ep = (uint32_t*)(g_epk + (size_t)((h * 16 + rowBlk) * 128)) ;
    // note: g_epk is uint4*, cast carefully below instead
    uint4* epb = g_epk + (size_t)(h * 16 + rowBlk) * 128 * 768;

    float sa = 0.f, sb = 0.f;
    for (int kb = w; kb < 128; kb += 8) {
        const int c0 = kb * 16 + t * 2;
        float2 A0 = *reinterpret_cast<const float2*>(&La[c0]);
        float2 B0 = *reinterpret_cast<const float2*>(&Lb[c0]);
        float2 A1 = *reinterpret_cast<const float2*>(&La[c0 + 8]);
        float2 B1 = *reinterpret_cast<const float2*>(&Lb[c0 + 8]);
        float2 cj0 = *reinterpret_cast<const float2*>(&cls[c0]);
        float2 cj1 = *reinterpret_cast<const float2*>(&cls[c0 + 8]);

        float e00 = (cj0.x > tha) ? __expf(A0.x * cj0.x) : 1.f;
        float e01 = (cj0.y > tha) ? __expf(A0.y * cj0.y) : 1.f;
        float e10 = (cj0.x > thb) ? __expf(B0.x * cj0.x) : 1.f;
        float e11 = (cj0.y > thb) ? __expf(B0.y * cj0.y) : 1.f;
        float e20 = (cj1.x > tha) ? __expf(A1.x * cj1.x) : 1.f;
        float e21 = (cj1.y > tha) ? __expf(A1.y * cj1.y) : 1.f;
        float e30 = (cj1.x > thb) ? __expf(B1.x * cj1.x) : 1.f;
        float e31 = (cj1.y > thb) ? __expf(B1.y * cj1.y) : 1.f;
        sa += e00 + e01 + e20 + e21;
        sb += e10 + e11 + e30 + e31;

        uint32_t h0,l0,h1,l1,h2,l2,h3,l3;
        split2(e00, e01, h0, l0);
        split2(e10, e11, h1, l1);
        split2(e20, e21, h2, l2);
        split2(e30, e31, h3, l3);
        uint32_t* tb = (uint32_t*)(epb + (size_t)kb * 768);
        const int bi = (m * 32 + lane) * 4;
        *reinterpret_cast<uint4*>(&tb[bi])        = make_uint4(h0, h1, h2, h3);
        *reinterpret_cast<uint4*>(&tb[1024 + bi]) = make_uint4(l0, l1, l2, l3);
    }
    (void)ep;
    sa += __shfl_xor_sync(0xffffffffu, sa, 1); sa += __shfl_xor_sync(0xffffffffu, sa, 2);
    sb += __shfl_xor_sync(0xffffffffu, sb, 1); sb += __shfl_xor_sync(0xffffffffu, sb, 2);
    __shared__ float rsm[8][16];
    if (t == 0) { rsm[w][g] = sa; rsm[w][8 + g] = sb; }
    __syncthreads();
    if (tid < 16) {
        float s = 0.f;
        #pragma unroll
        for (int w2 = 0; w2 < 8; w2++) s += rsm[w2][tid];
        g_rowsum[h * Nn + i0 + tid] = s;
    }
}

// ---------------- simround2 ----------------
__device__ __forceinline__ void accum8(const uint4* tb, int off, float ia, float ib, float v[8])
{
    uint4 H = tb[off], L = tb[256 + off];
    v[0] += (blo(H.x) + blo(L.x)) * ia;  v[1] += (bhi(H.x) + bhi(L.x)) * ia;
    v[2] += (blo(H.y) + blo(L.y)) * ib;  v[3] += (bhi(H.y) + bhi(L.y)) * ib;
    v[4] += (blo(H.z) + blo(L.z)) * ia;  v[5] += (bhi(H.z) + bhi(L.z)) * ia;
    v[6] += (blo(H.w) + blo(L.w)) * ib;  v[7] += (bhi(H.w) + bhi(L.w)) * ib;
}

__device__ __forceinline__ void calc_e(int kb, int rowBlk, int off,
                                       const float* ira, const float* irb, float e[8])
{
    float v[8];
    #pragma unroll
    for (int r = 0; r < 8; r++) v[r] = 0.f;
    #pragma unroll
    for (int h = 0; h < 8; h++)
        accum8(g_epk + (size_t)((h * 16 + rowBlk) * 128 + kb) * 768, off, ira[h], irb[h], v);
    #pragma unroll
    for (int r = 0; r < 8; r++) e[r] = __expf(v[r] * 0.125f);
}

__global__ __launch_bounds__(256) void simround2(float* __restrict__ out)
{
    const int a = blockIdx.x;
    const int i0 = a * 16, rowBlk = a >> 3, m = a & 7;
    const int tid = threadIdx.x, w = tid >> 5, lane = tid & 31;
    const int g = lane >> 2, t = lane & 3;
    const int ra = i0 + g, rb2 = ra + 8;
    const int off = m * 32 + lane;

    float ira[8], irb[8];
    #pragma unroll
    for (int h = 0; h < 8; h++) {
        ira[h] = 1.f / g_rowsum[h * Nn + ra];
        irb[h] = 1.f / g_rowsum[h * Nn + rb2];
    }
    const float* Sa = g_sim + (size_t)ra * Nn;
    const float* Sb = g_sim + (size_t)rb2 * Nn;

    // pass 1: masked exp sums (mask: sim_sum > 6.0)
    float S2a = 0.f, S2b = 0.f;
    for (int kb = w; kb < 128; kb += 8) {
        const int c0 = kb * 16 + t * 2;
        float e[8];
        calc_e(kb, rowBlk, off, ira, irb, e);
        float2 s0 = *reinterpret_cast<const float2*>(&Sa[c0]);
        float2 s1 = *reinterpret_cast<const float2*>(&Sb[c0]);
        float2 s2 = *reinterpret_cast<const float2*>(&Sa[c0 + 8]);
        float2 s3 = *reinterpret_cast<const float2*>(&Sb[c0 + 8]);
        S2a += (s0.x > 6.f ? e[0] : 0.f) + (s0.y > 6.f ? e[1] : 0.f)
             + (s2.x > 6.f ? e[4] : 0.f) + (s2.y > 6.f ? e[5] : 0.f);
        S2b += (s1.x > 6.f ? e[2] : 0.f) + (s1.y > 6.f ? e[3] : 0.f)
             + (s3.x > 6.f ? e[6] : 0.f) + (s3.y > 6.f ? e[7] : 0.f);
    }
    S2a += __shfl_xor_sync(0xffffffffu, S2a, 1); S2a += __shfl_xor_sync(0xffffffffu, S2a, 2);
    S2b += __shfl_xor_sync(0xffffffffu, S2b, 1); S2b += __shfl_xor_sync(0xffffffffu, S2b, 2);
    __shared__ float rsm[8][16];
    __shared__ float srow[16];
    if (t == 0) { rsm[w][g] = S2a; rsm[w][8 + g] = S2b; }
    __syncthreads();
    if (tid < 16) {
        float s = 0.f;
        #pragma unroll
        for (int w2 = 0; w2 < 8; w2++) s += rsm[w2][tid];
        srow[tid] = 1.f / s;
    }
    __syncthreads();
    const float i2a = srow[g], i2b = srow[8 + g];

    // pass 2: write out = mask * e / S2
    for (int kb = w; kb < 128; kb += 8) {
        const int c0 = kb * 16 + t * 2;
        float e[8];
        calc_e(kb, rowBlk, off, ira, irb, e);
        float2 s0 = *reinterpret_cast<const float2*>(&Sa[c0]);
        float2 s1 = *reinterpret_cast<const float2*>(&Sb[c0]);
        float2 s2 = *reinterpret_cast<const float2*>(&Sa[c0 + 8]);
        float2 s3 = *reinterpret_cast<const float2*>(&Sb[c0 + 8]);
        *reinterpret_cast<float2*>(&out[(size_t)ra * Nn + c0]) =
            make_float2(s0.x > 6.f ? e[0] * i2a : 0.f, s0.y > 6.f ? e[1] * i2a : 0.f);
        *reinterpret_cast<float2*>(&out[(size_t)rb2 * Nn + c0]) =
            make_float2(s1.x > 6.f ? e[2] * i2b : 0.f, s1.y > 6.f ? e[3] * i2b : 0.f);
        *reinterpret_cast<float2*>(&out[(size_t)ra * Nn + c0 + 8]) =
            make_float2(s2.x > 6.f ? e[4] * i2a : 0.f, s2.y > 6.f ? e[5] * i2a : 0.f);
        *reinterpret_cast<float2*>(&out[(size_t)rb2 * Nn + c0 + 8]) =
            make_float2(s3.x > 6.f ? e[6] * i2b : 0.f, s3.y > 6.f ? e[7] * i2b : 0.f);
    }
}

// ---------------- copy raw v into second half of x_out ----------------
__global__ __launch_bounds__(256) void copy_v_kernel(float* __restrict__ out)
{
    int idx = blockIdx.x * blockDim.x + threadIdx.x;
    if (idx >= Nn * Cc / 4) return;
    int n = idx / (Cc / 4);
    int c4 = idx % (Cc / 4);
    float4 v = *reinterpret_cast<const float4*>(&g_qkv[(size_t)n * (3 * Cc) + 2 * Cc + c4 * 4]);
    reinterpret_cast<float4*>(out)[(size_t)n * (2 * Cc / 4) + (Cc / 4) + c4] = v;
}

// ---------------- host launcher ----------------
extern "C" void kernel_launch(void* const* d_in, const int* in_sizes, int n_in,
                              void* d_out, int out_size)
{
    const float* x   = (const float*)d_in[0];
    const float* cls = (const float*)d_in[1];
    const float* W   = (const float*)d_in[3];
    float* out = (float*)d_out;

    float *p_qkv, *p_q, *p_k, *p_vn, *p_vT, *p_sim, *p_attn, *p_rs;
    uint4 *p_xpA, *p_WpB, *p_qpA, *p_kpB, *p_vnpA, *p_vnpB, *p_vTpB, *p_epk;
    cudaGetSymbolAddress((void**)&p_qkv, g_qkv);
    cudaGetSymbolAddress((void**)&p_q, g_q);
    cudaGetSymbolAddress((void**)&p_k, g_k);
    cudaGetSymbolAddress((void**)&p_vn, g_vn);
    cudaGetSymbolAddress((void**)&p_vT, g_vT);
    cudaGetSymbolAddress((void**)&p_sim, g_sim);
    cudaGetSymbolAddress((void**)&p_attn, g_attn);
    cudaGetSymbolAddress((void**)&p_rs, g_rowsum);
    cudaGetSymbolAddress((void**)&p_xpA, g_xpA);
    cudaGetSymbolAddress((void**)&p_WpB, g_WpB);
    cudaGetSymbolAddress((void**)&p_qpA, g_qpA);
    cudaGetSymbolAddress((void**)&p_kpB, g_kpB);
    cudaGetSymbolAddress((void**)&p_vnpA, g_vnpA);
    cudaGetSymbolAddress((void**)&p_vnpB, g_vnpB);
    cudaGetSymbolAddress((void**)&p_vTpB, g_vTpB);
    cudaGetSymbolAddress((void**)&p_epk, g_epk);

    // pack x, W
    pack_a3<<<dim3(64, 16, 1), 256>>>(x, Cc, 0, p_xpA, 64);
    pack_b3<<<dim3(64, 24, 1), 256>>>(W, Cc, 0, p_WpB, 64);

    // 1. qkv = x @ W^T (3-term for accuracy)
    gemm_pk<3><<<dim3(24, 16, 1), 256>>>(p_xpA, p_WpB, 64, p_qkv, 3 * Cc, 0, nullptr);

    // 2. normalize
    normalize_kernel<<<Nn, 256>>>();

    // 3. pack q, k, vn (A+B), vT
    pack_a3<<<dim3(8, 16, 8), 256>>>(p_q, HD, (long long)Nn * HD, p_qpA, 8);
    pack_b3<<<dim3(8, 16, 8), 256>>>(p_k, HD, (long long)Nn * HD, p_kpB, 8);
    pack_a3<<<dim3(64, 16, 1), 256>>>(p_vn, Cc, 0, p_vnpA, 64);
    pack_b3<<<dim3(64, 16, 1), 256>>>(p_vn, Cc, 0, p_vnpB, 64);
    pack_b3<<<dim3(128, 1, 8), 256>>>(p_vT, Nn, (long long)HD * Nn, p_vTpB, 128);

    // 4. sim = vn @ vn^T (head-summed via flat K=1024)
    gemm_pk<2><<<dim3(16, 16, 1), 256>>>(p_vnpA, p_vnpB, 64, p_sim, Nn, 0, nullptr);

    // 5. logits per head
    gemm_pk<2><<<dim3(16, 16, 8), 256>>>(p_qpA, p_kpB, 8, p_attn, Nn,
                                         (long long)Nn * Nn, nullptr);

    // 6. softmax -> packed e + rowsums
    softmax_pack<<<dim3(128, 8), 256>>>(cls);

    // 7. x = (e @ v) / rowsum  into first-half columns of x_out
    gemm_pk<2><<<dim3(1, 16, 8), 256>>>(p_epk, p_vTpB, 128, out, 2 * Cc, HD, p_rs);

    // 8. x_ori
    copy_v_kernel<<<(Nn * Cc / 4 + 255) / 256, 256>>>(out);

    // 9. sim_round2
    simround2<<<128, 256>>>(out + (size_t)Nn * 2 * Cc);
}

// round 5
// speedup vs baseline: 1.9290x; 1.4040x over previous
#include <cuda_runtime.h>
#include <math.h>
#include <stdint.h>

#define Nn 2048
#define Cc 1024
#define Hh 8
#define HD 128
#define SCALE_F 25.0f

// ---------------- scratch ----------------
__device__ float g_qkv[Nn * 3 * Cc];
__device__ float g_q[Hh * Nn * HD];
__device__ float g_k[Hh * Nn * HD];
__device__ float g_vn[Nn * Cc];
__device__ float g_vT[Hh * HD * Nn];
__device__ float g_sim[Nn * Nn];
__device__ float g_rowsum[Hh * Nn];

// packed 2-term bf16 fragment images; tile = 128 rows x 16 k.
// tile stride kept at 768 uint4 (image i at word offset i*1024; 2 images used).
__device__ uint4 g_xpA [(size_t)16 * 64 * 768];
__device__ uint4 g_WpB [(size_t)24 * 64 * 768];
__device__ uint4 g_qpA [(size_t)8 * 16 * 8 * 768];
__device__ uint4 g_kpB [(size_t)8 * 16 * 8 * 768];
__device__ uint4 g_vnpA[(size_t)16 * 64 * 768];
__device__ uint4 g_vnpB[(size_t)16 * 64 * 768];
__device__ uint4 g_vTpB[(size_t)8 * 128 * 768];
__device__ uint4 g_epk [(size_t)8 * 16 * 128 * 768];

// ---------------- helpers ----------------
__device__ __forceinline__ uint32_t packbf(float x, float y)
{
    uint32_t h;
    asm("cvt.rn.bf16x2.f32 %0, %1, %2;" : "=r"(h) : "f"(y), "f"(x));
    return h;
}
__device__ __forceinline__ float blo(uint32_t u) { return __uint_as_float(u << 16); }
__device__ __forceinline__ float bhi(uint32_t u) { return __uint_as_float(u & 0xFFFF0000u); }

__device__ __forceinline__ void split2(float x, float y, uint32_t& s0, uint32_t& s1)
{
    s0 = packbf(x, y);
    s1 = packbf(x - blo(s0), y - bhi(s0));
}

__device__ __forceinline__ void mma_bf16(float c[4], const uint32_t a[4],
                                         uint32_t b0, uint32_t b1)
{
    asm volatile(
        "mma.sync.aligned.m16n8k16.row.col.f32.bf16.bf16.f32 "
        "{%0,%1,%2,%3}, {%4,%5,%6,%7}, {%8,%9}, {%0,%1,%2,%3};"
        : "+f"(c[0]), "+f"(c[1]), "+f"(c[2]), "+f"(c[3])
        : "r"(a[0]), "r"(a[1]), "r"(a[2]), "r"(a[3]), "r"(b0), "r"(b1));
}

__device__ __forceinline__ void cpa16(void* smem, const void* gmem)
{
    uint32_t s = (uint32_t)__cvta_generic_to_shared(smem);
    asm volatile("cp.async.cg.shared.global [%0], [%1], 16;" :: "r"(s), "l"(gmem));
}
#define CP_COMMIT() asm volatile("cp.async.commit_group;")
#define CP_WAIT1()  asm volatile("cp.async.wait_group 1;")

// ---------------- pack kernels (fp32 -> 2-term bf16 fragment images) ----------------
__global__ __launch_bounds__(256) void pack_a2(
    const float* __restrict__ src, int lda, long long zstride, uint4* __restrict__ dst, int nKb)
{
    const int kb = blockIdx.x, rb = blockIdx.y, z = blockIdx.z;
    src += (long long)z * zstride;
    uint32_t* tb = (uint32_t*)(dst + ((size_t)(z * gridDim.y + rb) * nKb + kb) * 768);
    const int tid = threadIdx.x;
    #pragma unroll
    for (int t = 0; t < 2; t++) {
        int idx = tid + t * 256;
        int row = idx >> 2, k4 = (idx & 3) * 4;
        float4 v = *reinterpret_cast<const float4*>(
            &src[(long long)(rb * 128 + row) * lda + kb * 16 + k4]);
        int m = row >> 4, r16 = row & 15, g = r16 & 7, half = r16 >> 3;
        int tt = (k4 & 7) >> 1, reg = half + 2 * (k4 >> 3);
        int base = (m * 32 + g * 4 + tt) * 4 + reg;
        uint32_t s0, s1;
        split2(v.x, v.y, s0, s1);
        tb[base] = s0; tb[1024 + base] = s1;
        split2(v.z, v.w, s0, s1);
        tb[base + 4] = s0; tb[1024 + base + 4] = s1;
    }
}

__global__ __launch_bounds__(256) void pack_b2(
    const float* __restrict__ src, int ldb, long long zstride, uint4* __restrict__ dst, int nKb)
{
    const int kb = blockIdx.x, rb = blockIdx.y, z = blockIdx.z;
    src += (long long)z * zstride;
    uint32_t* tb = (uint32_t*)(dst + ((size_t)(z * gridDim.y + rb) * nKb + kb) * 768);
    const int tid = threadIdx.x;
    #pragma unroll
    for (int t = 0; t < 2; t++) {
        int idx = tid + t * 256;
        int row = idx >> 2, k4 = (idx & 3) * 4;
        float4 v = *reinterpret_cast<const float4*>(
            &src[(long long)(rb * 128 + row) * ldb + kb * 16 + k4]);
        int nb = row >> 3, g = row & 7;
        int tt = (k4 & 7) >> 1, reg = k4 >> 3;
        int base = (nb * 32 + g * 4 + tt) * 2 + reg;
        uint32_t s0, s1;
        split2(v.x, v.y, s0, s1);
        tb[base] = s0; tb[1024 + base] = s1;
        split2(v.z, v.w, s0, s1);
        tb[base + 2] = s0; tb[1024 + base + 2] = s1;
    }
}

// ---------------- packed 2-term bf16 GEMM, cp.async 3-stage pipeline ----------------
// MODE 0: plain store. MODE 1: store * 1/rowsum. MODE 2: logits -> masked exp,
//         packed e write (A-image) + atomic rowsums, no C store.
template<int MODE>
__global__ __launch_bounds__(256, 2) void gemm_pk(
    const uint4* __restrict__ At, const uint4* __restrict__ Bt, int nK,
    float* __restrict__ C, int ldc, long long cZ,
    const float* __restrict__ rs, const float* __restrict__ cls,
    uint4* __restrict__ epk, float* __restrict__ rsOut)
{
    const uint4* Ab = At + (size_t)(blockIdx.z * gridDim.y + blockIdx.y) * nK * 768;
    const uint4* Bb = Bt + (size_t)(blockIdx.z * gridDim.x + blockIdx.x) * nK * 768;

    __shared__ uint4 smA[3][512], smB[3][512];

    const int tid = threadIdx.x, lane = tid & 31, wid = tid >> 5;
    const int wm = wid >> 1, wn = wid & 1;

    float acc[2][8][4];
    #pragma unroll
    for (int mt = 0; mt < 2; mt++)
        #pragma unroll
        for (int nt = 0; nt < 8; nt++)
            #pragma unroll
            for (int r = 0; r < 4; r++) acc[mt][nt][r] = 0.f;

    // prologue: stages 0,1
    {
        const uint4* A0 = Ab;               const uint4* B0 = Bb;
        cpa16(&smA[0][tid], A0 + tid);       cpa16(&smA[0][256 + tid], A0 + 256 + tid);
        cpa16(&smB[0][tid], B0 + tid);       cpa16(&smB[0][256 + tid], B0 + 256 + tid);
        CP_COMMIT();
        const uint4* A1 = Ab + 768;          const uint4* B1 = Bb + 768;
        cpa16(&smA[1][tid], A1 + tid);       cpa16(&smA[1][256 + tid], A1 + 256 + tid);
        cpa16(&smB[1][tid], B1 + tid);       cpa16(&smB[1][256 + tid], B1 + 256 + tid);
        CP_COMMIT();
    }

    int cur = 0;
    for (int kb = 0; kb < nK; kb++) {
        CP_WAIT1();
        __syncthreads();

        uint32_t af[2][2][4];
        #pragma unroll
        for (int i = 0; i < 2; i++)
            #pragma unroll
            for (int mt = 0; mt < 2; mt++)
                *reinterpret_cast<uint4*>(af[i][mt]) =
                    smA[cur][i * 256 + (wm * 2 + mt) * 32 + lane];

        const uint2* B2 = reinterpret_cast<const uint2*>(smB[cur]);
        #pragma unroll
        for (int nt = 0; nt < 8; nt++) {
            uint2 b0 = B2[(wn * 8 + nt) * 32 + lane];
            uint2 b1 = B2[512 + (wn * 8 + nt) * 32 + lane];
            #pragma unroll
            for (int mt = 0; mt < 2; mt++) {
                mma_bf16(acc[mt][nt], af[0][mt], b0.x, b0.y);  // hi*hi
                mma_bf16(acc[mt][nt], af[1][mt], b0.x, b0.y);  // lo*hi
                mma_bf16(acc[mt][nt], af[0][mt], b1.x, b1.y);  // hi*lo
            }
        }

        if (kb + 2 < nK) {
            const int st = (kb + 2) % 3;
            const uint4* An = Ab + (size_t)(kb + 2) * 768;
            const uint4* Bn = Bb + (size_t)(kb + 2) * 768;
            cpa16(&smA[st][tid], An + tid);       cpa16(&smA[st][256 + tid], An + 256 + tid);
            cpa16(&smB[st][tid], Bn + tid);       cpa16(&smB[st][256 + tid], Bn + 256 + tid);
        }
        CP_COMMIT();
        cur = (cur + 1 == 3) ? 0 : cur + 1;
    }

    const int g = lane >> 2, tq = lane & 3;

    if (MODE == 2) {
        // masked exp + packed e write + rowsums
        #pragma unroll
        for (int mt = 0; mt < 2; mt++) {
            const int m = wm * 2 + mt;
            const int i0 = blockIdx.y * 128 + m * 16 + g;
            const int i1 = i0 + 8;
            const float tha = cls[i0] - 0.1f;
            const float thb = cls[i1] - 0.1f;
            float rs0 = 0.f, rs1 = 0.f;
            #pragma unroll
            for (int nt = 0; nt < 8; nt++) {
                const int j = blockIdx.x * 128 + wn * 64 + nt * 8 + tq * 2;
                const float cj0 = cls[j], cj1 = cls[j + 1];
                float e00 = (cj0 > tha) ? __expf(acc[mt][nt][0] * cj0) : 1.f;
                float e01 = (cj1 > tha) ? __expf(acc[mt][nt][1] * cj1) : 1.f;
                float e10 = (cj0 > thb) ? __expf(acc[mt][nt][2] * cj0) : 1.f;
                float e11 = (cj1 > thb) ? __expf(acc[mt][nt][3] * cj1) : 1.f;
                rs0 += e00 + e01;
                rs1 += e10 + e11;
                const size_t tIdx = (size_t)(blockIdx.z * 16 + blockIdx.y) * 128
                                  + blockIdx.x * 8 + ((wn * 8 + nt) >> 1);
                uint32_t* tb = (uint32_t*)(epk + tIdx * 768);
                const int w = (m * 32 + g * 4 + tq) * 4 + 2 * (nt & 1);
                uint32_t h0, l0, h1, l1;
                split2(e00, e01, h0, l0);
                split2(e10, e11, h1, l1);
                tb[w]            = h0;
                tb[1024 + w]     = l0;
                tb[w + 1]        = h1;
                tb[1024 + w + 1] = l1;
            }
            rs0 += __shfl_xor_sync(0xffffffffu, rs0, 1);
            rs0 += __shfl_xor_sync(0xffffffffu, rs0, 2);
            rs1 += __shfl_xor_sync(0xffffffffu, rs1, 1);
            rs1 += __shfl_xor_sync(0xffffffffu, rs1, 2);
            if (tq == 0) {
                atomicAdd(&rsOut[blockIdx.z * Nn + i0], rs0);
                atomicAdd(&rsOut[blockIdx.z * Nn + i1], rs1);
            }
        }
    } else {
        float* Cz = C + (long long)blockIdx.z * cZ;
        #pragma unroll
        for (int mt = 0; mt < 2; mt++) {
            const int row0 = blockIdx.y * 128 + wm * 32 + mt * 16 + g;
            float s0 = 1.f, s1 = 1.f;
            if (MODE == 1) {
                s0 = 1.f / rs[blockIdx.z * Nn + row0];
                s1 = 1.f / rs[blockIdx.z * Nn + row0 + 8];
            }
            #pragma unroll
            for (int nt = 0; nt < 8; nt++) {
                const int col = blockIdx.x * 128 + wn * 64 + nt * 8 + tq * 2;
                *reinterpret_cast<float2*>(&Cz[(long long)row0 * ldc + col]) =
                    make_float2(acc[mt][nt][0] * s0, acc[mt][nt][1] * s0);
                *reinterpret_cast<float2*>(&Cz[(long long)(row0 + 8) * ldc + col]) =
                    make_float2(acc[mt][nt][2] * s1, acc[mt][nt][3] * s1);
            }
        }
    }
}

// ---------------- normalize ----------------
__global__ __launch_bounds__(256) void normalize_kernel()
{
    const int n = blockIdx.x;
    const int w = threadIdx.x >> 5;
    const int lane = threadIdx.x & 31;
    const float* base = g_qkv + (long long)n * (3 * Cc);

    float qv[4], kv[4], vv[4];
    #pragma unroll
    for (int r = 0; r < 4; r++) {
        int d = lane + 32 * r;
        qv[r] = base[0 * Cc + w * HD + d];
        kv[r] = base[1 * Cc + w * HD + d];
        vv[r] = base[2 * Cc + w * HD + d];
    }
    float sq = 0.f, sk = 0.f, sv = 0.f;
    #pragma unroll
    for (int r = 0; r < 4; r++) { sq += qv[r]*qv[r]; sk += kv[r]*kv[r]; sv += vv[r]*vv[r]; }
    #pragma unroll
    for (int o = 16; o > 0; o >>= 1) {
        sq += __shfl_xor_sync(0xffffffffu, sq, o);
        sk += __shfl_xor_sync(0xffffffffu, sk, o);
        sv += __shfl_xor_sync(0xffffffffu, sv, o);
    }
    const float iq = SCALE_F / sqrtf(sq);
    const float ik = 1.0f / sqrtf(sk);
    const float iv = 1.0f / sqrtf(sv);
    #pragma unroll
    for (int r = 0; r < 4; r++) {
        int d = lane + 32 * r;
        g_q[(long long)w * Nn * HD + (long long)n * HD + d] = qv[r] * iq;
        g_k[(long long)w * Nn * HD + (long long)n * HD + d] = kv[r] * ik;
        g_vn[(long long)n * Cc + w * HD + d] = vv[r] * iv;
        g_vT[(long long)w * HD * Nn + (long long)d * Nn + n] = vv[r];
    }
}

// ---------------- simround2 ----------------
__device__ __forceinline__ void accum8(const uint4* tb, int off, float ia, float ib, float v[8])
{
    uint4 H = tb[off], L = tb[256 + off];
    v[0] += (blo(H.x) + blo(L.x)) * ia;  v[1] += (bhi(H.x) + bhi(L.x)) * ia;
    v[2] += (blo(H.y) + blo(L.y)) * ib;  v[3] += (bhi(H.y) + bhi(L.y)) * ib;
    v[4] += (blo(H.z) + blo(L.z)) * ia;  v[5] += (bhi(H.z) + bhi(L.z)) * ia;
    v[6] += (blo(H.w) + blo(L.w)) * ib;  v[7] += (bhi(H.w) + bhi(L.w)) * ib;
}

__device__ __forceinline__ void calc_e(int kb, int rowBlk, int off,
                                       const float* ira, const float* irb, float e[8])
{
    float v[8];
    #pragma unroll
    for (int r = 0; r < 8; r++) v[r] = 0.f;
    #pragma unroll
    for (int h = 0; h < 8; h++)
        accum8(g_epk + (size_t)((h * 16 + rowBlk) * 128 + kb) * 768, off, ira[h], irb[h], v);
    #pragma unroll
    for (int r = 0; r < 8; r++) e[r] = __expf(v[r] * 0.125f);
}

__global__ __launch_bounds__(256) void simround2(float* __restrict__ out)
{
    const int a = blockIdx.x;
    const int i0 = a * 16, rowBlk = a >> 3, m = a & 7;
    const int tid = threadIdx.x, w = tid >> 5, lane = tid & 31;
    const int g = lane >> 2, t = lane & 3;
    const int ra = i0 + g, rb2 = ra + 8;
    const int off = m * 32 + lane;

    float ira[8], irb[8];
    #pragma unroll
    for (int h = 0; h < 8; h++) {
        ira[h] = 1.f / g_rowsum[h * Nn + ra];
        irb[h] = 1.f / g_rowsum[h * Nn + rb2];
    }
    const float* Sa = g_sim + (size_t)ra * Nn;
    const float* Sb = g_sim + (size_t)rb2 * Nn;

    float S2a = 0.f, S2b = 0.f;
    for (int kb = w; kb < 128; kb += 8) {
        const int c0 = kb * 16 + t * 2;
        float e[8];
        calc_e(kb, rowBlk, off, ira, irb, e);
        float2 s0 = *reinterpret_cast<const float2*>(&Sa[c0]);
        float2 s1 = *reinterpret_cast<const float2*>(&Sb[c0]);
        float2 s2 = *reinterpret_cast<const float2*>(&Sa[c0 + 8]);
        float2 s3 = *reinterpret_cast<const float2*>(&Sb[c0 + 8]);
        S2a += (s0.x > 6.f ? e[0] : 0.f) + (s0.y > 6.f ? e[1] : 0.f)
             + (s2.x > 6.f ? e[4] : 0.f) + (s2.y > 6.f ? e[5] : 0.f);
        S2b += (s1.x > 6.f ? e[2] : 0.f) + (s1.y > 6.f ? e[3] : 0.f)
             + (s3.x > 6.f ? e[6] : 0.f) + (s3.y > 6.f ? e[7] : 0.f);
    }
    S2a += __shfl_xor_sync(0xffffffffu, S2a, 1); S2a += __shfl_xor_sync(0xffffffffu, S2a, 2);
    S2b += __shfl_xor_sync(0xffffffffu, S2b, 1); S2b += __shfl_xor_sync(0xffffffffu, S2b, 2);
    __shared__ float rsm[8][16];
    __shared__ float srow[16];
    if (t == 0) { rsm[w][g] = S2a; rsm[w][8 + g] = S2b; }
    __syncthreads();
    if (tid < 16) {
        float s = 0.f;
        #pragma unroll
        for (int w2 = 0; w2 < 8; w2++) s += rsm[w2][tid];
        srow[tid] = 1.f / s;
    }
    __syncthreads();
    const float i2a = srow[g], i2b = srow[8 + g];

    for (int kb = w; kb < 128; kb += 8) {
        const int c0 = kb * 16 + t * 2;
        float e[8];
        calc_e(kb, rowBlk, off, ira, irb, e);
        float2 s0 = *reinterpret_cast<const float2*>(&Sa[c0]);
        float2 s1 = *reinterpret_cast<const float2*>(&Sb[c0]);
        float2 s2 = *reinterpret_cast<const float2*>(&Sa[c0 + 8]);
        float2 s3 = *reinterpret_cast<const float2*>(&Sb[c0 + 8]);
        *reinterpret_cast<float2*>(&out[(size_t)ra * Nn + c0]) =
            make_float2(s0.x > 6.f ? e[0] * i2a : 0.f, s0.y > 6.f ? e[1] * i2a : 0.f);
        *reinterpret_cast<float2*>(&out[(size_t)rb2 * Nn + c0]) =
            make_float2(s1.x > 6.f ? e[2] * i2b : 0.f, s1.y > 6.f ? e[3] * i2b : 0.f);
        *reinterpret_cast<float2*>(&out[(size_t)ra * Nn + c0 + 8]) =
            make_float2(s2.x > 6.f ? e[4] * i2a : 0.f, s2.y > 6.f ? e[5] * i2a : 0.f);
        *reinterpret_cast<float2*>(&out[(size_t)rb2 * Nn + c0 + 8]) =
            make_float2(s3.x > 6.f ? e[6] * i2b : 0.f, s3.y > 6.f ? e[7] * i2b : 0.f);
    }
}

// ---------------- copy raw v into second half of x_out ----------------
__global__ __launch_bounds__(256) void copy_v_kernel(float* __restrict__ out)
{
    int idx = blockIdx.x * blockDim.x + threadIdx.x;
    if (idx >= Nn * Cc / 4) return;
    int n = idx / (Cc / 4);
    int c4 = idx % (Cc / 4);
    float4 v = *reinterpret_cast<const float4*>(&g_qkv[(size_t)n * (3 * Cc) + 2 * Cc + c4 * 4]);
    reinterpret_cast<float4*>(out)[(size_t)n * (2 * Cc / 4) + (Cc / 4) + c4] = v;
}

// ---------------- host launcher ----------------
extern "C" void kernel_launch(void* const* d_in, const int* in_sizes, int n_in,
                              void* d_out, int out_size)
{
    const float* x   = (const float*)d_in[0];
    const float* cls = (const float*)d_in[1];
    const float* W   = (const float*)d_in[3];
    float* out = (float*)d_out;

    float *p_qkv, *p_q, *p_k, *p_vn, *p_vT, *p_sim, *p_rs;
    uint4 *p_xpA, *p_WpB, *p_qpA, *p_kpB, *p_vnpA, *p_vnpB, *p_vTpB, *p_epk;
    cudaGetSymbolAddress((void**)&p_qkv, g_qkv);
    cudaGetSymbolAddress((void**)&p_q, g_q);
    cudaGetSymbolAddress((void**)&p_k, g_k);
    cudaGetSymbolAddress((void**)&p_vn, g_vn);
    cudaGetSymbolAddress((void**)&p_vT, g_vT);
    cudaGetSymbolAddress((void**)&p_sim, g_sim);
    cudaGetSymbolAddress((void**)&p_rs, g_rowsum);
    cudaGetSymbolAddress((void**)&p_xpA, g_xpA);
    cudaGetSymbolAddress((void**)&p_WpB, g_WpB);
    cudaGetSymbolAddress((void**)&p_qpA, g_qpA);
    cudaGetSymbolAddress((void**)&p_kpB, g_kpB);
    cudaGetSymbolAddress((void**)&p_vnpA, g_vnpA);
    cudaGetSymbolAddress((void**)&p_vnpB, g_vnpB);
    cudaGetSymbolAddress((void**)&p_vTpB, g_vTpB);
    cudaGetSymbolAddress((void**)&p_epk, g_epk);

    // pack x, W (2-term)
    pack_a2<<<dim3(64, 16, 1), 256>>>(x, Cc, 0, p_xpA, 64);
    pack_b2<<<dim3(64, 24, 1), 256>>>(W, Cc, 0, p_WpB, 64);

    // 1. qkv = x @ W^T (2-term, 3 products)
    gemm_pk<0><<<dim3(24, 16, 1), 256>>>(p_xpA, p_WpB, 64, p_qkv, 3 * Cc, 0,
                                         nullptr, nullptr, nullptr, nullptr);

    // 2. normalize
    normalize_kernel<<<Nn, 256>>>();

    // 3. pack q, k, vn (A+B), vT
    pack_a2<<<dim3(8, 16, 8), 256>>>(p_q, HD, (long long)Nn * HD, p_qpA, 8);
    pack_b2<<<dim3(8, 16, 8), 256>>>(p_k, HD, (long long)Nn * HD, p_kpB, 8);
    pack_a2<<<dim3(64, 16, 1), 256>>>(p_vn, Cc, 0, p_vnpA, 64);
    pack_b2<<<dim3(64, 16, 1), 256>>>(p_vn, Cc, 0, p_vnpB, 64);
    pack_b2<<<dim3(128, 1, 8), 256>>>(p_vT, Nn, (long long)HD * Nn, p_vTpB, 128);

    // 4. sim = vn @ vn^T (head-summed via flat K=1024)
    gemm_pk<0><<<dim3(16, 16, 1), 256>>>(p_vnpA, p_vnpB, 64, p_sim, Nn, 0,
                                         nullptr, nullptr, nullptr, nullptr);

    // 5. zero rowsums, then logits GEMM with fused mask/exp/pack epilogue
    cudaMemsetAsync(p_rs, 0, Hh * Nn * sizeof(float));
    gemm_pk<2><<<dim3(16, 16, 8), 256>>>(p_qpA, p_kpB, 8, nullptr, 0, 0,
                                         nullptr, cls, p_epk, p_rs);

    // 6. x = (e @ v) / rowsum  into first-half columns of x_out
    gemm_pk<1><<<dim3(1, 16, 8), 256>>>(p_epk, p_vTpB, 128, out, 2 * Cc, HD,
                                        p_rs, nullptr, nullptr, nullptr);

    // 7. x_ori
    copy_v_kernel<<<(Nn * Cc / 4 + 255) / 256, 256>>>(out);

    // 8. sim_round2
    simround2<<<128, 256>>>(out + (size_t)Nn * 2 * Cc);
}

// round 7
// speedup vs baseline: 2.2121x; 1.1467x over previous
#include <cuda_runtime.h>
#include <math.h>
#include <stdint.h>

#define Nn 2048
#define Cc 1024
#define Hh 8
#define HD 128
#define SCALE_F 25.0f

// ---------------- scratch ----------------
__device__ float g_qkv[Nn * 3 * Cc];
__device__ float g_q[Hh * Nn * HD];
__device__ float g_k[Hh * Nn * HD];
__device__ float g_vn[Nn * Cc];
__device__ float g_vT[Hh * HD * Nn];
__device__ float g_rowsum[Hh * Nn];
__device__ float g_part[(size_t)32 * Nn * HD];   // attn@V split-K partials
__device__ float g_es[(size_t)Nn * Nn];
__device__ float g_srow[Nn];
__device__ uint8_t g_mask[(size_t)Nn * Nn];

// packed 2-term bf16 fragment images; tile = 128 rows x 16 k (stride 768 uint4)
__device__ uint4 g_xp [(size_t)16 * 64 * 768];
__device__ uint4 g_Wp [(size_t)24 * 64 * 768];
__device__ uint4 g_qp [(size_t)8 * 16 * 8 * 768];
__device__ uint4 g_kp [(size_t)8 * 16 * 8 * 768];
__device__ uint4 g_vnpA[(size_t)16 * 64 * 768];
__device__ uint4 g_vnpB[(size_t)16 * 64 * 768];
__device__ uint4 g_vTp[(size_t)8 * 128 * 768];
__device__ uint4 g_epk[(size_t)8 * 16 * 128 * 768];

// ---------------- helpers ----------------
__device__ __forceinline__ uint32_t packbf(float x, float y)
{
    uint32_t h;
    asm("cvt.rn.bf16x2.f32 %0, %1, %2;" : "=r"(h) : "f"(y), "f"(x));
    return h;
}
__device__ __forceinline__ float blo(uint32_t u) { return __uint_as_float(u << 16); }
__device__ __forceinline__ float bhi(uint32_t u) { return __uint_as_float(u & 0xFFFF0000u); }
__device__ __forceinline__ void split2(float x, float y, uint32_t& s0, uint32_t& s1)
{
    s0 = packbf(x, y);
    s1 = packbf(x - blo(s0), y - bhi(s0));
}

__device__ __forceinline__ void mma_bf16(float c[4], const uint32_t a[4],
                                         uint32_t b0, uint32_t b1)
{
    asm volatile(
        "mma.sync.aligned.m16n8k16.row.col.f32.bf16.bf16.f32 "
        "{%0,%1,%2,%3}, {%4,%5,%6,%7}, {%8,%9}, {%0,%1,%2,%3};"
        : "+f"(c[0]), "+f"(c[1]), "+f"(c[2]), "+f"(c[3])
        : "r"(a[0]), "r"(a[1]), "r"(a[2]), "r"(a[3]), "r"(b0), "r"(b1));
}

__device__ __forceinline__ void cpa16(void* smem, const void* gmem)
{
    uint32_t s = (uint32_t)__cvta_generic_to_shared(smem);
    asm volatile("cp.async.cg.shared.global [%0], [%1], 16;" :: "r"(s), "l"(gmem));
}
#define CP_COMMIT() asm volatile("cp.async.commit_group;")
#define CP_WAIT1()  asm volatile("cp.async.wait_group 1;")
#define CP_WAIT0()  asm volatile("cp.async.wait_group 0;")

// ---------------- pack kernels (fp32 -> 2-term bf16 fragment images) ----------------
__global__ __launch_bounds__(256) void pack_a2(
    const float* __restrict__ src, int lda, long long zstride, uint4* __restrict__ dst, int nKb)
{
    const int kb = blockIdx.x, rb = blockIdx.y, z = blockIdx.z;
    src += (long long)z * zstride;
    uint32_t* tb = (uint32_t*)(dst + ((size_t)(z * gridDim.y + rb) * nKb + kb) * 768);
    const int tid = threadIdx.x;
    #pragma unroll
    for (int t = 0; t < 2; t++) {
        int idx = tid + t * 256;
        int row = idx >> 2, k4 = (idx & 3) * 4;
        float4 v = *reinterpret_cast<const float4*>(
            &src[(long long)(rb * 128 + row) * lda + kb * 16 + k4]);
        int m = row >> 4, r16 = row & 15, g = r16 & 7, half = r16 >> 3;
        int tt = (k4 & 7) >> 1, reg = half + 2 * (k4 >> 3);
        int base = (m * 32 + g * 4 + tt) * 4 + reg;
        uint32_t s0, s1;
        split2(v.x, v.y, s0, s1);
        tb[base] = s0; tb[1024 + base] = s1;
        split2(v.z, v.w, s0, s1);
        tb[base + 4] = s0; tb[1024 + base + 4] = s1;
    }
}

__global__ __launch_bounds__(256) void pack_b2(
    const float* __restrict__ src, int ldb, long long zstride, uint4* __restrict__ dst, int nKb)
{
    const int kb = blockIdx.x, rb = blockIdx.y, z = blockIdx.z;
    src += (long long)z * zstride;
    uint32_t* tb = (uint32_t*)(dst + ((size_t)(z * gridDim.y + rb) * nKb + kb) * 768);
    const int tid = threadIdx.x;
    #pragma unroll
    for (int t = 0; t < 2; t++) {
        int idx = tid + t * 256;
        int row = idx >> 2, k4 = (idx & 3) * 4;
        float4 v = *reinterpret_cast<const float4*>(
            &src[(long long)(rb * 128 + row) * ldb + kb * 16 + k4]);
        int nb = row >> 3, g = row & 7;
        int tt = (k4 & 7) >> 1, reg = k4 >> 3;
        int base = (nb * 32 + g * 4 + tt) * 2 + reg;
        uint32_t s0, s1;
        split2(v.x, v.y, s0, s1);
        tb[base] = s0; tb[1024 + base] = s1;
        split2(v.z, v.w, s0, s1);
        tb[base + 2] = s0; tb[1024 + base + 2] = s1;
    }
}

// ---------------- packed 2-term bf16 GEMM, cp.async 3-stage ----------------
// MODE 0: plain fp32 store (C + z*cZ).
// MODE 2: logits -> masked exp, packed e (A-image) + atomic rowsums.
// MODE 3: symmetric sim -> mask bytes (C>6) for tile (by,bx) AND (bx,by).
template<int MODE>
__global__ __launch_bounds__(256, 2) void gemm_pk(
    const uint4* __restrict__ At, const uint4* __restrict__ Bt,
    int nK, int nKtotA, int nKtotB, int nRbA, int nRbB, int kzBits,
    float* __restrict__ C, int ldc, long long cZ,
    const float* __restrict__ cls, uint4* __restrict__ epk,
    float* __restrict__ rsOut, uint8_t* __restrict__ maskOut)
{
    int bx, by;
    if (MODE == 3) {
        int r = blockIdx.x, row = 0;
        while (r >= 16 - row) { r -= 16 - row; row++; }
        by = row; bx = row + r;
    } else { bx = blockIdx.x; by = blockIdx.y; }

    const int hz = blockIdx.z >> kzBits;
    const int kz = blockIdx.z & ((1 << kzBits) - 1);
    const uint4* Ab = At + ((size_t)(hz * nRbA + by) * nKtotA + (size_t)kz * nK) * 768;
    const uint4* Bb = Bt + ((size_t)(hz * nRbB + bx) * nKtotB + (size_t)kz * nK) * 768;

    __shared__ uint4 smA[3][512], smB[3][512];

    const int tid = threadIdx.x, lane = tid & 31, wid = tid >> 5;
    const int wm = wid >> 1, wn = wid & 1;

    float acc[2][8][4];
    #pragma unroll
    for (int mt = 0; mt < 2; mt++)
        #pragma unroll
        for (int nt = 0; nt < 8; nt++)
            #pragma unroll
            for (int r = 0; r < 4; r++) acc[mt][nt][r] = 0.f;

    // prologue
    {
        cpa16(&smA[0][tid], Ab + tid);             cpa16(&smA[0][256 + tid], Ab + 256 + tid);
        cpa16(&smB[0][tid], Bb + tid);             cpa16(&smB[0][256 + tid], Bb + 256 + tid);
        CP_COMMIT();
        const uint4* A1 = Ab + 768;                const uint4* B1 = Bb + 768;
        cpa16(&smA[1][tid], A1 + tid);             cpa16(&smA[1][256 + tid], A1 + 256 + tid);
        cpa16(&smB[1][tid], B1 + tid);             cpa16(&smB[1][256 + tid], B1 + 256 + tid);
        CP_COMMIT();
    }

    int cur = 0;
    for (int kb = 0; kb < nK; kb++) {
        if (kb + 2 <= nK) CP_WAIT1(); else CP_WAIT0();
        __syncthreads();

        uint32_t af[2][2][4];
        #pragma unroll
        for (int i = 0; i < 2; i++)
            #pragma unroll
            for (int mt = 0; mt < 2; mt++)
                *reinterpret_cast<uint4*>(af[i][mt]) =
                    smA[cur][i * 256 + (wm * 2 + mt) * 32 + lane];

        const uint2* B2 = reinterpret_cast<const uint2*>(smB[cur]);
        #pragma unroll
        for (int nt = 0; nt < 8; nt++) {
            uint2 b0 = B2[(wn * 8 + nt) * 32 + lane];
            uint2 b1 = B2[512 + (wn * 8 + nt) * 32 + lane];
            #pragma unroll
            for (int mt = 0; mt < 2; mt++) {
                mma_bf16(acc[mt][nt], af[0][mt], b0.x, b0.y);
                mma_bf16(acc[mt][nt], af[1][mt], b0.x, b0.y);
                mma_bf16(acc[mt][nt], af[0][mt], b1.x, b1.y);
            }
        }

        if (kb + 2 < nK) {
            const int st = (kb + 2) % 3;
            const uint4* An = Ab + (size_t)(kb + 2) * 768;
            const uint4* Bn = Bb + (size_t)(kb + 2) * 768;
            cpa16(&smA[st][tid], An + tid);        cpa16(&smA[st][256 + tid], An + 256 + tid);
            cpa16(&smB[st][tid], Bn + tid);        cpa16(&smB[st][256 + tid], Bn + 256 + tid);
        }
        CP_COMMIT();
        cur = (cur + 1 == 3) ? 0 : cur + 1;
    }

    const int g = lane >> 2, tq = lane & 3;

    if (MODE == 2) {
        #pragma unroll
        for (int mt = 0; mt < 2; mt++) {
            const int m = wm * 2 + mt;
            const int i0 = by * 128 + m * 16 + g;
            const int i1 = i0 + 8;
            const float tha = cls[i0] - 0.1f;
            const float thb = cls[i1] - 0.1f;
            float rs0 = 0.f, rs1 = 0.f;
            #pragma unroll
            for (int nt = 0; nt < 8; nt++) {
                const int j = bx * 128 + wn * 64 + nt * 8 + tq * 2;
                const float cj0 = cls[j], cj1 = cls[j + 1];
                float e00 = (cj0 > tha) ? __expf(acc[mt][nt][0] * cj0) : 1.f;
                float e01 = (cj1 > tha) ? __expf(acc[mt][nt][1] * cj1) : 1.f;
                float e10 = (cj0 > thb) ? __expf(acc[mt][nt][2] * cj0) : 1.f;
                float e11 = (cj1 > thb) ? __expf(acc[mt][nt][3] * cj1) : 1.f;
                rs0 += e00 + e01;
                rs1 += e10 + e11;
                const size_t tIdx = (size_t)(hz * 16 + by) * 128
                                  + bx * 8 + ((wn * 8 + nt) >> 1);
                uint32_t* tb = (uint32_t*)(epk + tIdx * 768);
                const int w = (m * 32 + g * 4 + tq) * 4 + 2 * (nt & 1);
                uint32_t h0, l0, h1, l1;
                split2(e00, e01, h0, l0);
                split2(e10, e11, h1, l1);
                tb[w]            = h0;
                tb[1024 + w]     = l0;
                tb[w + 1]        = h1;
                tb[1024 + w + 1] = l1;
            }
            rs0 += __shfl_xor_sync(0xffffffffu, rs0, 1);
            rs0 += __shfl_xor_sync(0xffffffffu, rs0, 2);
            rs1 += __shfl_xor_sync(0xffffffffu, rs1, 1);
            rs1 += __shfl_xor_sync(0xffffffffu, rs1, 2);
            if (tq == 0) {
                atomicAdd(&rsOut[hz * Nn + i0], rs0);
                atomicAdd(&rsOut[hz * Nn + i1], rs1);
            }
        }
    } else if (MODE == 3) {
        __syncthreads();                           // mainloop smem reads done
        uint8_t* sb = reinterpret_cast<uint8_t*>(smA);   // 128 x 144 byte tile
        #pragma unroll
        for (int mt = 0; mt < 2; mt++)
            #pragma unroll
            for (int nt = 0; nt < 8; nt++) {
                const int r0 = wm * 32 + mt * 16 + g;
                const int c0 = wn * 64 + nt * 8 + tq * 2;
                sb[r0 * 144 + c0]           = acc[mt][nt][0] > 6.f;
                sb[r0 * 144 + c0 + 1]       = acc[mt][nt][1] > 6.f;
                sb[(r0 + 8) * 144 + c0]     = acc[mt][nt][2] > 6.f;
                sb[(r0 + 8) * 144 + c0 + 1] = acc[mt][nt][3] > 6.f;
            }
        __syncthreads();
        const int r = tid >> 1, hf = tid & 1;
        {   // normal tile
            const uint8_t* srcp = sb + r * 144 + hf * 64;
            uint4 v0 = *reinterpret_cast<const uint4*>(srcp);
            uint4 v1 = *reinterpret_cast<const uint4*>(srcp + 16);
            uint4 v2 = *reinterpret_cast<const uint4*>(srcp + 32);
            uint4 v3 = *reinterpret_cast<const uint4*>(srcp + 48);
            uint8_t* dst = maskOut + (size_t)(by * 128 + r) * Nn + bx * 128 + hf * 64;
            *reinterpret_cast<uint4*>(dst)      = v0;
            *reinterpret_cast<uint4*>(dst + 16) = v1;
            *reinterpret_cast<uint4*>(dst + 32) = v2;
            *reinterpret_cast<uint4*>(dst + 48) = v3;
        }
        {   // transposed tile
            uint32_t wv[16];
            #pragma unroll
            for (int q = 0; q < 16; q++) {
                uint32_t b0 = sb[(hf * 64 + q * 4 + 0) * 144 + r];
                uint32_t b1 = sb[(hf * 64 + q * 4 + 1) * 144 + r];
                uint32_t b2 = sb[(hf * 64 + q * 4 + 2) * 144 + r];
                uint32_t b3 = sb[(hf * 64 + q * 4 + 3) * 144 + r];
                wv[q] = b0 | (b1 << 8) | (b2 << 16) | (b3 << 24);
            }
            uint8_t* dst = maskOut + (size_t)(bx * 128 + r) * Nn + by * 128 + hf * 64;
            #pragma unroll
            for (int q = 0; q < 4; q++)
                *reinterpret_cast<uint4*>(dst + q * 16) =
                    make_uint4(wv[q*4], wv[q*4+1], wv[q*4+2], wv[q*4+3]);
        }
    } else {
        float* Cz = C + (long long)blockIdx.z * cZ;
        #pragma unroll
        for (int mt = 0; mt < 2; mt++) {
            const int row0 = by * 128 + wm * 32 + mt * 16 + g;
            #pragma unroll
            for (int nt = 0; nt < 8; nt++) {
                const int col = bx * 128 + wn * 64 + nt * 8 + tq * 2;
                *reinterpret_cast<float2*>(&Cz[(long long)row0 * ldc + col]) =
                    make_float2(acc[mt][nt][0], acc[mt][nt][1]);
                *reinterpret_cast<float2*>(&Cz[(long long)(row0 + 8) * ldc + col]) =
                    make_float2(acc[mt][nt][2], acc[mt][nt][3]);
            }
        }
    }
}

// ---------------- normalize ----------------
__global__ __launch_bounds__(256) void normalize_kernel()
{
    const int n = blockIdx.x;
    const int w = threadIdx.x >> 5;
    const int lane = threadIdx.x & 31;
    const float* base = g_qkv + (long long)n * (3 * Cc);

    float qv[4], kv[4], vv[4];
    #pragma unroll
    for (int r = 0; r < 4; r++) {
        int d = lane + 32 * r;
        qv[r] = base[0 * Cc + w * HD + d];
        kv[r] = base[1 * Cc + w * HD + d];
        vv[r] = base[2 * Cc + w * HD + d];
    }
    float sq = 0.f, sk = 0.f, sv = 0.f;
    #pragma unroll
    for (int r = 0; r < 4; r++) { sq += qv[r]*qv[r]; sk += kv[r]*kv[r]; sv += vv[r]*vv[r]; }
    #pragma unroll
    for (int o = 16; o > 0; o >>= 1) {
        sq += __shfl_xor_sync(0xffffffffu, sq, o);
        sk += __shfl_xor_sync(0xffffffffu, sk, o);
        sv += __shfl_xor_sync(0xffffffffu, sv, o);
    }
    const float iq = SCALE_F / sqrtf(sq);
    const float ik = 1.0f / sqrtf(sk);
    const float iv = 1.0f / sqrtf(sv);
    #pragma unroll
    for (int r = 0; r < 4; r++) {
        int d = lane + 32 * r;
        g_q[(long long)w * Nn * HD + (long long)n * HD + d] = qv[r] * iq;
        g_k[(long long)w * Nn * HD + (long long)n * HD + d] = kv[r] * ik;
        g_vn[(long long)n * Cc + w * HD + d] = vv[r] * iv;
        g_vT[(long long)w * HD * Nn + (long long)d * Nn + n] = vv[r];
    }
}

// ---------------- combine split-K partials: out = (sum kz) / rowsum ----------------
__global__ __launch_bounds__(256) void combine_kernel(float* __restrict__ out)
{
    int idx = blockIdx.x * 256 + threadIdx.x;
    if (idx >= Nn * Cc / 4) return;
    const int n = idx >> 8, c4 = idx & 255;
    const int h = c4 >> 5, d4 = c4 & 31;
    const float4* p = reinterpret_cast<const float4*>(g_part);
    const size_t st = (size_t)Nn * 32;
    const size_t b = ((size_t)(h * 4) * Nn + n) * 32 + d4;
    float4 a0 = p[b], a1 = p[b + st], a2 = p[b + 2 * st], a3 = p[b + 3 * st];
    const float s = 1.f / g_rowsum[h * Nn + n];
    *reinterpret_cast<float4*>(out + (size_t)n * (2 * Cc) + h * 128 + d4 * 4) =
        make_float4((a0.x + a1.x + a2.x + a3.x) * s, (a0.y + a1.y + a2.y + a3.y) * s,
                    (a0.z + a1.z + a2.z + a3.z) * s, (a0.w + a1.w + a2.w + a3.w) * s);
}

// ---------------- simround2 pass1: es + masked row sums (single epk read) ----------------
__global__ __launch_bounds__(256) void simr2_pass1()
{
    const int blk = blockIdx.x;                // 0..127
    const int tid = threadIdx.x;
    const int rl = tid >> 4, ct = tid & 15;
    const int i = blk * 16 + rl;
    const int rowBlk = i >> 7, il = i & 127;
    const int m = il >> 4, rg = il & 15, g = rg & 7, half = rg >> 3;
    const int ubase = m * 32 + g * 4;

    float irs[8];
    #pragma unroll
    for (int h = 0; h < 8; h++) irs[h] = 1.f / g_rowsum[h * Nn + i];

    float msum = 0.f;
    for (int kt = 0; kt < 8; kt++) {
        const int kb = ct + kt * 16;
        float acc[16];
        #pragma unroll
        for (int p = 0; p < 16; p++) acc[p] = 0.f;
        #pragma unroll
        for (int h = 0; h < 8; h++) {
            const uint4* blob = g_epk + ((size_t)((h * 16 + rowBlk) * 128 + kb)) * 768;
            const float w = irs[h];
            #pragma unroll
            for (int t = 0; t < 4; t++) {
                uint4 H = blob[ubase + t], L = blob[256 + ubase + t];
                uint32_t h0 = half ? H.y : H.x, l0 = half ? L.y : L.x;
                uint32_t h1 = half ? H.w : H.z, l1 = half ? L.w : L.z;
                acc[t*2+0]     += (blo(h0) + blo(l0)) * w;
                acc[t*2+1]     += (bhi(h0) + bhi(l0)) * w;
                acc[8+t*2+0]   += (blo(h1) + blo(l1)) * w;
                acc[8+t*2+1]   += (bhi(h1) + bhi(l1)) * w;
            }
        }
        const int j0 = kb * 16;
        uint4 mbv = *reinterpret_cast<const uint4*>(g_mask + (size_t)i * Nn + j0);
        const uint8_t* mb = reinterpret_cast<const uint8_t*>(&mbv);
        float* dst = g_es + (size_t)i * Nn + j0;
        #pragma unroll
        for (int kh = 0; kh < 2; kh++)
            #pragma unroll
            for (int t = 0; t < 4; t++) {
                float e0 = __expf(acc[kh*8 + t*2]     * 0.125f);
                float e1 = __expf(acc[kh*8 + t*2 + 1] * 0.125f);
                const int col = kh * 8 + t * 2;
                if (mb[col])     msum += e0;
                if (mb[col + 1]) msum += e1;
                *reinterpret_cast<float2*>(dst + col) = make_float2(e0, e1);
            }
    }
    #pragma unroll
    for (int o = 1; o < 16; o <<= 1) msum += __shfl_xor_sync(0xffffffffu, msum, o);
    if (ct == 0) g_srow[i] = msum;
}

// ---------------- simround2 pass2: out = mask * es / srow ----------------
__global__ __launch_bounds__(256) void simr2_pass2(float* __restrict__ out)
{
    int idx = blockIdx.x * blockDim.x + threadIdx.x;
    if (idx >= Nn * Nn / 4) return;
    const int i = idx >> 9;
    const int j = (idx & 511) * 4;
    const float inv = 1.f / g_srow[i];
    uchar4 m = *reinterpret_cast<const uchar4*>(g_mask + (size_t)i * Nn + j);
    float4 e = *reinterpret_cast<const float4*>(g_es + (size_t)i * Nn + j);
    *reinterpret_cast<float4*>(out + (size_t)i * Nn + j) = make_float4(
        m.x ? e.x * inv : 0.f, m.y ? e.y * inv : 0.f,
        m.z ? e.z * inv : 0.f, m.w ? e.w * inv : 0.f);
}

// ---------------- copy raw v into second half of x_out ----------------
__global__ __launch_bounds__(256) void copy_v_kernel(float* __restrict__ out)
{
    int idx = blockIdx.x * blockDim.x + threadIdx.x;
    if (idx >= Nn * Cc / 4) return;
    int n = idx / (Cc / 4);
    int c4 = idx % (Cc / 4);
    float4 v = *reinterpret_cast<const float4*>(&g_qkv[(size_t)n * (3 * Cc) + 2 * Cc + c4 * 4]);
    reinterpret_cast<float4*>(out)[(size_t)n * (2 * Cc / 4) + (Cc / 4) + c4] = v;
}

// ---------------- host launcher ----------------
extern "C" void kernel_launch(void* const* d_in, const int* in_sizes, int n_in,
                              void* d_out, int out_size)
{
    const float* x   = (const float*)d_in[0];
    const float* cls = (const float*)d_in[1];
    const float* W   = (const float*)d_in[3];
    float* out = (float*)d_out;

    float *p_qkv, *p_q, *p_k, *p_vn, *p_vT, *p_rs, *p_part;
    uint4 *p_xp, *p_Wp, *p_qp, *p_kp, *p_vnpA, *p_vnpB, *p_vTp, *p_epk;
    uint8_t* p_mask;
    cudaGetSymbolAddress((void**)&p_qkv, g_qkv);
    cudaGetSymbolAddress((void**)&p_q, g_q);
    cudaGetSymbolAddress((void**)&p_k, g_k);
    cudaGetSymbolAddress((void**)&p_vn, g_vn);
    cudaGetSymbolAddress((void**)&p_vT, g_vT);
    cudaGetSymbolAddress((void**)&p_rs, g_rowsum);
    cudaGetSymbolAddress((void**)&p_part, g_part);
    cudaGetSymbolAddress((void**)&p_xp, g_xp);
    cudaGetSymbolAddress((void**)&p_Wp, g_Wp);
    cudaGetSymbolAddress((void**)&p_qp, g_qp);
    cudaGetSymbolAddress((void**)&p_kp, g_kp);
    cudaGetSymbolAddress((void**)&p_vnpA, g_vnpA);
    cudaGetSymbolAddress((void**)&p_vnpB, g_vnpB);
    cudaGetSymbolAddress((void**)&p_vTp, g_vTp);
    cudaGetSymbolAddress((void**)&p_epk, g_epk);
    cudaGetSymbolAddress((void**)&p_mask, g_mask);

    // pack x, W
    pack_a2<<<dim3(64, 16, 1), 256>>>(x, Cc, 0, p_xp, 64);
    pack_b2<<<dim3(64, 24, 1), 256>>>(W, Cc, 0, p_Wp, 64);

    // 1. qkv = x @ W^T
    gemm_pk<0><<<dim3(24, 16, 1), 256>>>(p_xp, p_Wp, 64, 64, 64, 16, 24, 0,
                                         p_qkv, 3 * Cc, 0, nullptr, nullptr, nullptr, nullptr);

    // 2. normalize
    normalize_kernel<<<Nn, 256>>>();

    // 3. pack q, k, vn (A+B), vT
    pack_a2<<<dim3(8, 16, 8), 256>>>(p_q, HD, (long long)Nn * HD, p_qp, 8);
    pack_b2<<<dim3(8, 16, 8), 256>>>(p_k, HD, (long long)Nn * HD, p_kp, 8);
    pack_a2<<<dim3(64, 16, 1), 256>>>(p_vn, Cc, 0, p_vnpA, 64);
    pack_b2<<<dim3(64, 16, 1), 256>>>(p_vn, Cc, 0, p_vnpB, 64);
    pack_b2<<<dim3(128, 1, 8), 256>>>(p_vT, Nn, (long long)HD * Nn, p_vTp, 128);

    // 4. sim mask (symmetric upper-triangle tiles): mask = (vn @ vn^T > 6)
    gemm_pk<3><<<dim3(136, 1, 1), 256>>>(p_vnpA, p_vnpB, 64, 64, 64, 16, 16, 0,
                                         nullptr, 0, 0, nullptr, nullptr, nullptr, p_mask);

    // 5. logits + fused masked-exp -> packed e + rowsums
    cudaMemsetAsync(p_rs, 0, Hh * Nn * sizeof(float));
    gemm_pk<2><<<dim3(16, 16, 8), 256>>>(p_qp, p_kp, 8, 8, 8, 16, 16, 0,
                                         nullptr, 0, 0, cls, p_epk, p_rs, nullptr);

    // 6. attn@V split-K x4 -> partials
    gemm_pk<0><<<dim3(1, 16, 32), 256>>>(p_epk, p_vTp, 32, 128, 128, 16, 1, 2,
                                         p_part, HD, (long long)Nn * HD,
                                         nullptr, nullptr, nullptr, nullptr);

    // 7. combine partials / rowsum into first-half columns of x_out
    combine_kernel<<<(Nn * Cc / 4 + 255) / 256, 256>>>(out);

    // 8. x_ori
    copy_v_kernel<<<(Nn * Cc / 4 + 255) / 256, 256>>>(out);

    // 9. sim_round2
    simr2_pass1<<<128, 256>>>();
    simr2_pass2<<<(Nn * Nn / 4 + 255) / 256, 256>>>(out + (size_t)Nn * 2 * Cc);
}